// round 12
// baseline (speedup 1.0000x reference)
#include <cuda_runtime.h>
#include <cuda_bf16.h>
#include <cstdint>

#define D 128
#define NMAX 50048
#define EMAX 800000

// ---------------- scratch (static device allocations; no cudaMalloc) --------
__device__ float g_q[(size_t)NMAX * D];
__device__ float g_k[(size_t)NMAX * D];
__device__ float g_v[(size_t)NMAX * D];
__device__ float g_agg[(size_t)NMAX * D];
__device__ int   g_cnt[NMAX];
__device__ int   g_offs[NMAX + 1];
__device__ int   g_cur[NMAX];
__device__ int   g_src[EMAX];
__device__ int   g_is64;

// ---------------- edge dtype detection --------------------------------------
__global__ void detect_kernel(const void* ei, int e) {
    const long long* p = (const long long*)ei;
    int lim = (2 * e < 16) ? 2 * e : 16;
    int ok = 1;
    for (int i = 0; i < lim; ++i) {
        long long v = p[i];
        if (v < 0 || v >= NMAX) { ok = 0; break; }
    }
    g_is64 = ok;
}
__device__ __forceinline__ int load_edge(const void* ei, size_t idx, int is64) {
    if (is64) return (int)((const long long*)ei)[idx];
    return ((const int*)ei)[idx];
}

// ---------------- mma.sync bf16 helpers (base ISA, sm_80+) -------------------
__device__ __forceinline__ uint32_t smem_u32(const void* p) {
    uint32_t a;
    asm("{ .reg .u64 t; cvta.to.shared.u64 t, %1; cvt.u32.u64 %0, t; }" : "=r"(a) : "l"(p));
    return a;
}
__device__ __forceinline__ void ldm_x4(uint32_t r[4], uint32_t addr) {
    asm volatile("ldmatrix.sync.aligned.m8n8.x4.shared.b16 {%0,%1,%2,%3}, [%4];"
                 : "=r"(r[0]), "=r"(r[1]), "=r"(r[2]), "=r"(r[3]) : "r"(addr));
}
__device__ __forceinline__ void mma_bf16(float d[4], const uint32_t a[4], const uint32_t b[2]) {
    asm volatile(
        "mma.sync.aligned.m16n8k16.row.col.f32.bf16.bf16.f32 "
        "{%0,%1,%2,%3}, {%4,%5,%6,%7}, {%8,%9}, {%0,%1,%2,%3};"
        : "+f"(d[0]), "+f"(d[1]), "+f"(d[2]), "+f"(d[3])
        : "r"(a[0]), "r"(a[1]), "r"(a[2]), "r"(a[3]), "r"(b[0]), "r"(b[1]));
}

// split fp32x4 -> bf16 hi (packed 2x u32) + bf16 lo
__device__ __forceinline__ void split4(float4 x, uint2& h, uint2& l) {
    __nv_bfloat16 hx = __float2bfloat16_rn(x.x);
    __nv_bfloat16 hy = __float2bfloat16_rn(x.y);
    __nv_bfloat16 hz = __float2bfloat16_rn(x.z);
    __nv_bfloat16 hw = __float2bfloat16_rn(x.w);
    __nv_bfloat16 lx = __float2bfloat16_rn(x.x - __bfloat162float(hx));
    __nv_bfloat16 ly = __float2bfloat16_rn(x.y - __bfloat162float(hy));
    __nv_bfloat16 lz = __float2bfloat16_rn(x.z - __bfloat162float(hz));
    __nv_bfloat16 lw = __float2bfloat16_rn(x.w - __bfloat162float(hw));
    h.x = (uint32_t)__bfloat16_as_ushort(hx) | ((uint32_t)__bfloat16_as_ushort(hy) << 16);
    h.y = (uint32_t)__bfloat16_as_ushort(hz) | ((uint32_t)__bfloat16_as_ushort(hw) << 16);
    l.x = (uint32_t)__bfloat16_as_ushort(lx) | ((uint32_t)__bfloat16_as_ushort(ly) << 16);
    l.y = (uint32_t)__bfloat16_as_ushort(lz) | ((uint32_t)__bfloat16_as_ushort(lw) << 16);
}

// ---------------- HMMA 3xBF16 GEMM: C[M x 128] = A @ W^T + bias -------------
#define ROWB 272
#define OFF_AHI 0
#define OFF_ALO (128 * ROWB)
#define OFF_BHI (2 * 128 * ROWB)
#define OFF_BLO (3 * 128 * ROWB)
#define OFF_BIAS (4 * 128 * ROWB)
#define GEMM_SMEM (OFF_BIAS + 512)

__global__ __launch_bounds__(256, 1)
void hmma_gemm_kernel(const float* Aext, int asel,
                      const float* __restrict__ w0, const float* __restrict__ w1,
                      const float* __restrict__ w2,
                      const float* __restrict__ b0, const float* __restrict__ b1,
                      const float* __restrict__ b2,
                      float* Cext, int cbase, int M) {
    extern __shared__ char smem[];
    const uint32_t sb = smem_u32(smem);

    const int sel = blockIdx.y;
    const float* A    = asel ? g_agg : Aext;
    const float* Bw   = (sel == 0) ? w0 : (sel == 1) ? w1 : w2;
    const float* bias = (sel == 0) ? b0 : (sel == 1) ? b1 : b2;
    const int csel = cbase + sel;
    float* C = (csel == 0) ? g_q : (csel == 1) ? g_k : (csel == 2) ? g_v : Cext;

    const int tid  = threadIdx.x;
    const int wid  = tid >> 5;
    const int lane = tid & 31;
    const int block_row = blockIdx.x * 128;
    const int wm = wid & 3;
    const int wn = wid >> 2;

    if (tid < 128) *(float*)(smem + OFF_BIAS + tid * 4) = bias[tid];
    for (int i = tid; i < 4096; i += 256) {
        int row = i >> 5;
        int k4  = (i & 31) << 2;
        uint32_t sboff = (uint32_t)row * ROWB + k4 * 2;
        float4 x = make_float4(0.f, 0.f, 0.f, 0.f);
        int gr = block_row + row;
        if (gr < M) x = *(const float4*)(A + (size_t)gr * D + k4);
        uint2 h, l;
        split4(x, h, l);
        *(uint2*)(smem + OFF_AHI + sboff) = h;
        *(uint2*)(smem + OFF_ALO + sboff) = l;
        float4 b = *(const float4*)(Bw + (size_t)row * D + k4);
        split4(b, h, l);
        *(uint2*)(smem + OFF_BHI + sboff) = h;
        *(uint2*)(smem + OFF_BLO + sboff) = l;
    }
    __syncthreads();

    float acc[2][8][4];
#pragma unroll
    for (int mt = 0; mt < 2; mt++)
#pragma unroll
        for (int nt = 0; nt < 8; nt++)
#pragma unroll
            for (int c = 0; c < 4; c++) acc[mt][nt][c] = 0.f;

    const int li = lane & 7;
    const int lq = lane >> 3;

    for (int ks = 0; ks < 8; ks++) {
        const int k0 = ks * 16;
        uint32_t ah[2][4], al[2][4];
#pragma unroll
        for (int mt = 0; mt < 2; mt++) {
            int row = wm * 32 + mt * 16 + li + (lq & 1) * 8;
            int col = k0 + (lq >> 1) * 8;
            uint32_t off = (uint32_t)row * ROWB + col * 2;
            ldm_x4(ah[mt], sb + OFF_AHI + off);
            ldm_x4(al[mt], sb + OFF_ALO + off);
        }
#pragma unroll
        for (int np = 0; np < 4; np++) {
            int row = wn * 64 + np * 16 + li + (lq >> 1) * 8;
            int col = k0 + (lq & 1) * 8;
            uint32_t off = (uint32_t)row * ROWB + col * 2;
            uint32_t bh[4], bl[4];
            ldm_x4(bh, sb + OFF_BHI + off);
            ldm_x4(bl, sb + OFF_BLO + off);
#pragma unroll
            for (int mt = 0; mt < 2; mt++) {
                mma_bf16(acc[mt][2 * np + 0], ah[mt], &bh[0]);
                mma_bf16(acc[mt][2 * np + 0], ah[mt], &bl[0]);
                mma_bf16(acc[mt][2 * np + 0], al[mt], &bh[0]);
                mma_bf16(acc[mt][2 * np + 1], ah[mt], &bh[2]);
                mma_bf16(acc[mt][2 * np + 1], ah[mt], &bl[2]);
                mma_bf16(acc[mt][2 * np + 1], al[mt], &bh[2]);
            }
        }
    }

    const int tg = lane >> 2;
    const int tc = (lane & 3) * 2;
#pragma unroll
    for (int mt = 0; mt < 2; mt++) {
        int r0 = block_row + wm * 32 + mt * 16 + tg;
#pragma unroll
        for (int nt = 0; nt < 8; nt++) {
            int col = wn * 64 + nt * 8 + tc;
            float bx = *(float*)(smem + OFF_BIAS + col * 4);
            float by = *(float*)(smem + OFF_BIAS + (col + 1) * 4);
            if (r0 < M) {
                float2 o; o.x = acc[mt][nt][0] + bx; o.y = acc[mt][nt][1] + by;
                *(float2*)(C + (size_t)r0 * D + col) = o;
            }
            if (r0 + 8 < M) {
                float2 o; o.x = acc[mt][nt][2] + bx; o.y = acc[mt][nt][3] + by;
                *(float2*)(C + (size_t)(r0 + 8) * D + col) = o;
            }
        }
    }
}

// ---------------- CSR build --------------------------------------------------
__global__ void zero_cnt_kernel(int n) {
    for (int i = blockIdx.x * blockDim.x + threadIdx.x; i < n; i += gridDim.x * blockDim.x)
        g_cnt[i] = 0;
}
__global__ void hist_kernel(const void* __restrict__ ei, int e, int n) {
    int is64 = g_is64;
    for (int idx = blockIdx.x * blockDim.x + threadIdx.x; idx < e; idx += gridDim.x * blockDim.x) {
        int c = load_edge(ei, 2 * (size_t)idx + 1, is64);
        if ((unsigned)c < (unsigned)n) atomicAdd(&g_cnt[c], 1);
    }
}
__global__ void scan_kernel(int n) {
    __shared__ int warpsum[32];
    int tid  = threadIdx.x;
    int lane = tid & 31;
    int wid  = tid >> 5;
    int carry = 0;
    for (int base = 0; base < n; base += 1024) {
        int i = base + tid;
        int x = (i < n) ? g_cnt[i] : 0;
        int s = x;
#pragma unroll
        for (int off = 1; off < 32; off <<= 1) {
            int t2 = __shfl_up_sync(0xffffffffu, s, off);
            if (lane >= off) s += t2;
        }
        if (lane == 31) warpsum[wid] = s;
        __syncthreads();
        if (wid == 0) {
            int ws = warpsum[lane];
#pragma unroll
            for (int off = 1; off < 32; off <<= 1) {
                int t2 = __shfl_up_sync(0xffffffffu, ws, off);
                if (lane >= off) ws += t2;
            }
            warpsum[lane] = ws;
        }
        __syncthreads();
        int prefix = (wid > 0) ? warpsum[wid - 1] : 0;
        int excl   = s + prefix - x;
        if (i < n) {
            g_offs[i] = carry + excl;
            g_cur[i]  = carry + excl;
        }
        int total = warpsum[31];
        __syncthreads();
        carry += total;
    }
    if (tid == 0) g_offs[n] = carry;
}
__global__ void scatter_kernel(const void* __restrict__ ei, int e, int n) {
    int is64 = g_is64;
    for (int idx = blockIdx.x * blockDim.x + threadIdx.x; idx < e; idx += gridDim.x * blockDim.x) {
        int r = load_edge(ei, 2 * (size_t)idx + 0, is64);
        int c = load_edge(ei, 2 * (size_t)idx + 1, is64);
        if ((unsigned)c < (unsigned)n && (unsigned)r < (unsigned)n) {
            int pos = atomicAdd(&g_cur[c], 1);
            if ((unsigned)pos < (unsigned)EMAX) g_src[pos] = r;
        }
    }
}

// ---------------- fused per-node attention: WARP per node --------------------
// Lane owns 4 contiguous dims (head = lane/4). 2 x LDG.128 per edge per warp,
// 2-shfl score reduce within 4-lane head groups, online softmax with implicit
// zero logit (m=0, l=1). 8 nodes per 256-thread block.
__global__ __launch_bounds__(256)
void attn_kernel(int n) {
    int node = blockIdx.x * 8 + (threadIdx.x >> 5);
    if (node >= n) return;
    int lane = threadIdx.x & 31;
    int dim  = lane << 2;

    float4 q4 = *(const float4*)(g_q + (size_t)node * D + dim);
    q4.x *= 0.25f; q4.y *= 0.25f; q4.z *= 0.25f; q4.w *= 0.25f;

    int beg = g_offs[node];
    int end = g_offs[node + 1];

    float m = 0.f, l = 1.f;
    float4 acc = make_float4(0.f, 0.f, 0.f, 0.f);

    int r1 = (beg + 1 < end) ? g_src[beg + 1] : 0;
    float4 k4 = make_float4(0.f, 0.f, 0.f, 0.f);
    float4 v4 = k4;
    if (beg < end) {
        int r0 = g_src[beg];
        k4 = *(const float4*)(g_k + (size_t)r0 * D + dim);
        v4 = *(const float4*)(g_v + (size_t)r0 * D + dim);
    }

    for (int j = beg; j < end; ++j) {
        int r2 = (j + 2 < end) ? g_src[j + 2] : 0;
        float4 kn = *(const float4*)(g_k + (size_t)r1 * D + dim);
        float4 vn = *(const float4*)(g_v + (size_t)r1 * D + dim);

        float p = q4.x * k4.x + q4.y * k4.y + q4.z * k4.z + q4.w * k4.w;
        p += __shfl_xor_sync(0xffffffffu, p, 2);
        p += __shfl_xor_sync(0xffffffffu, p, 1);
        // p = head score (same on all 4 lanes of the head group)

        float nm = fmaxf(m, p);
        float sc = __expf(m - nm);
        float pe = __expf(p - nm);
        l = l * sc + pe;
        acc.x = acc.x * sc + pe * v4.x;
        acc.y = acc.y * sc + pe * v4.y;
        acc.z = acc.z * sc + pe * v4.z;
        acc.w = acc.w * sc + pe * v4.w;
        m = nm;

        k4 = kn; v4 = vn; r1 = r2;
    }

    float inv = 1.f / (l * fmaxf((float)(end - beg), 1.f));
    float4 o;
    o.x = acc.x * inv; o.y = acc.y * inv; o.z = acc.z * inv; o.w = acc.w * inv;
    *(float4*)(g_agg + (size_t)node * D + dim) = o;
}

// ---------------- launch -----------------------------------------------------
extern "C" void kernel_launch(void* const* d_in, const int* in_sizes, int n_in,
                              void* d_out, int out_size) {
    const float* feats = (const float*)d_in[0];
    const void*  ei    = d_in[1];
    const float* Wq = (const float*)d_in[2];
    const float* bq = (const float*)d_in[3];
    const float* Wk = (const float*)d_in[4];
    const float* bk = (const float*)d_in[5];
    const float* Wv = (const float*)d_in[6];
    const float* bv = (const float*)d_in[7];
    const float* Wo = (const float*)d_in[8];
    const float* bo = (const float*)d_in[9];
    float* out = (float*)d_out;

    int n = in_sizes[0] / D;
    int e = in_sizes[1] / 2;
    if (n > NMAX || e > EMAX || n <= 0) return;

    cudaFuncSetAttribute(hmma_gemm_kernel,
                         cudaFuncAttributeMaxDynamicSharedMemorySize, GEMM_SMEM);

    // 0) detect edge_index dtype
    detect_kernel<<<1, 1>>>(ei, e);

    // 1) Q/K/V projections in ONE launch (gridDim.y = 3)
    int gblocks = (n + 127) / 128;
    hmma_gemm_kernel<<<dim3(gblocks, 3), 256, GEMM_SMEM>>>(
        feats, 0, Wq, Wk, Wv, bq, bk, bv, nullptr, 0, n);

    // 2) CSR by destination
    zero_cnt_kernel<<<(n + 255) / 256, 256>>>(n);
    hist_kernel<<<(e + 255) / 256, 256>>>(ei, e, n);
    scan_kernel<<<1, 1024>>>(n);
    scatter_kernel<<<(e + 255) / 256, 256>>>(ei, e, n);

    // 3) fused edge softmax + aggregation (warp per node)
    attn_kernel<<<(n + 7) / 8, 256>>>(n);

    // 4) output projection -> d_out
    hmma_gemm_kernel<<<dim3(gblocks, 1), 256, GEMM_SMEM>>>(
        nullptr, 1, Wo, Wo, Wo, bo, bo, bo, out, 3, n);
}

// round 13
// speedup vs baseline: 1.4589x; 1.4589x over previous
#include <cuda_runtime.h>
#include <cuda_bf16.h>
#include <cuda_fp16.h>
#include <cstdint>

#define D 128
#define NMAX 50048
#define EMAX 800000

// ---------------- scratch (static device allocations; no cudaMalloc) --------
__device__ float    g_q[(size_t)NMAX * D];
__device__ uint32_t g_kh[(size_t)NMAX * (D / 2)];   // fp16x2 per entry
__device__ uint32_t g_vh[(size_t)NMAX * (D / 2)];
__device__ float    g_agg[(size_t)NMAX * D];
__device__ int      g_cnt[NMAX];
__device__ int      g_offs[NMAX + 1];
__device__ int      g_cur[NMAX];
__device__ int      g_src[EMAX];
__device__ int      g_is64;

// ---------------- edge dtype handling ---------------------------------------
__device__ __forceinline__ int load_edge(const void* ei, size_t idx, int is64) {
    if (is64) return (int)((const long long*)ei)[idx];
    return ((const int*)ei)[idx];
}

// ---------------- mma.sync bf16 helpers (base ISA, sm_80+) -------------------
__device__ __forceinline__ uint32_t smem_u32(const void* p) {
    uint32_t a;
    asm("{ .reg .u64 t; cvta.to.shared.u64 t, %1; cvt.u32.u64 %0, t; }" : "=r"(a) : "l"(p));
    return a;
}
__device__ __forceinline__ void ldm_x4(uint32_t r[4], uint32_t addr) {
    asm volatile("ldmatrix.sync.aligned.m8n8.x4.shared.b16 {%0,%1,%2,%3}, [%4];"
                 : "=r"(r[0]), "=r"(r[1]), "=r"(r[2]), "=r"(r[3]) : "r"(addr));
}
__device__ __forceinline__ void mma_bf16(float d[4], const uint32_t a[4], const uint32_t b[2]) {
    asm volatile(
        "mma.sync.aligned.m16n8k16.row.col.f32.bf16.bf16.f32 "
        "{%0,%1,%2,%3}, {%4,%5,%6,%7}, {%8,%9}, {%0,%1,%2,%3};"
        : "+f"(d[0]), "+f"(d[1]), "+f"(d[2]), "+f"(d[3])
        : "r"(a[0]), "r"(a[1]), "r"(a[2]), "r"(a[3]), "r"(b[0]), "r"(b[1]));
}

// split fp32x4 -> bf16 hi (packed 2x u32) + bf16 lo
__device__ __forceinline__ void split4(float4 x, uint2& h, uint2& l) {
    __nv_bfloat16 hx = __float2bfloat16_rn(x.x);
    __nv_bfloat16 hy = __float2bfloat16_rn(x.y);
    __nv_bfloat16 hz = __float2bfloat16_rn(x.z);
    __nv_bfloat16 hw = __float2bfloat16_rn(x.w);
    __nv_bfloat16 lx = __float2bfloat16_rn(x.x - __bfloat162float(hx));
    __nv_bfloat16 ly = __float2bfloat16_rn(x.y - __bfloat162float(hy));
    __nv_bfloat16 lz = __float2bfloat16_rn(x.z - __bfloat162float(hz));
    __nv_bfloat16 lw = __float2bfloat16_rn(x.w - __bfloat162float(hw));
    h.x = (uint32_t)__bfloat16_as_ushort(hx) | ((uint32_t)__bfloat16_as_ushort(hy) << 16);
    h.y = (uint32_t)__bfloat16_as_ushort(hz) | ((uint32_t)__bfloat16_as_ushort(hw) << 16);
    l.x = (uint32_t)__bfloat16_as_ushort(lx) | ((uint32_t)__bfloat16_as_ushort(ly) << 16);
    l.y = (uint32_t)__bfloat16_as_ushort(lz) | ((uint32_t)__bfloat16_as_ushort(lw) << 16);
}

// ---------------- HMMA 3xBF16 GEMM: C[M x 128] = A @ W^T + bias -------------
// csel: 0 -> g_q (fp32), 1 -> g_kh (fp16), 2 -> g_vh (fp16), 3 -> Cext (fp32)
#define ROWB 272
#define OFF_AHI 0
#define OFF_ALO (128 * ROWB)
#define OFF_BHI (2 * 128 * ROWB)
#define OFF_BLO (3 * 128 * ROWB)
#define OFF_BIAS (4 * 128 * ROWB)
#define GEMM_SMEM (OFF_BIAS + 512)

__global__ __launch_bounds__(256, 1)
void hmma_gemm_kernel(const float* Aext, int asel,
                      const float* __restrict__ w0, const float* __restrict__ w1,
                      const float* __restrict__ w2,
                      const float* __restrict__ b0, const float* __restrict__ b1,
                      const float* __restrict__ b2,
                      float* Cext, int cbase, int M) {
    extern __shared__ char smem[];
    const uint32_t sb = smem_u32(smem);

    const int sel = blockIdx.y;
    const float* A    = asel ? g_agg : Aext;
    const float* Bw   = (sel == 0) ? w0 : (sel == 1) ? w1 : w2;
    const float* bias = (sel == 0) ? b0 : (sel == 1) ? b1 : b2;
    const int csel = cbase + sel;
    float*    Cf = (csel == 0) ? g_q : Cext;
    uint32_t* Ch = (csel == 1) ? g_kh : g_vh;
    const bool half_out = (csel == 1 || csel == 2);

    const int tid  = threadIdx.x;
    const int wid  = tid >> 5;
    const int lane = tid & 31;
    const int block_row = blockIdx.x * 128;
    const int wm = wid & 3;
    const int wn = wid >> 2;

    if (tid < 128) *(float*)(smem + OFF_BIAS + tid * 4) = bias[tid];
    for (int i = tid; i < 4096; i += 256) {
        int row = i >> 5;
        int k4  = (i & 31) << 2;
        uint32_t sboff = (uint32_t)row * ROWB + k4 * 2;
        float4 x = make_float4(0.f, 0.f, 0.f, 0.f);
        int gr = block_row + row;
        if (gr < M) x = *(const float4*)(A + (size_t)gr * D + k4);
        uint2 h, l;
        split4(x, h, l);
        *(uint2*)(smem + OFF_AHI + sboff) = h;
        *(uint2*)(smem + OFF_ALO + sboff) = l;
        float4 b = *(const float4*)(Bw + (size_t)row * D + k4);
        split4(b, h, l);
        *(uint2*)(smem + OFF_BHI + sboff) = h;
        *(uint2*)(smem + OFF_BLO + sboff) = l;
    }
    __syncthreads();

    float acc[2][8][4];
#pragma unroll
    for (int mt = 0; mt < 2; mt++)
#pragma unroll
        for (int nt = 0; nt < 8; nt++)
#pragma unroll
            for (int c = 0; c < 4; c++) acc[mt][nt][c] = 0.f;

    const int li = lane & 7;
    const int lq = lane >> 3;

    for (int ks = 0; ks < 8; ks++) {
        const int k0 = ks * 16;
        uint32_t ah[2][4], al[2][4];
#pragma unroll
        for (int mt = 0; mt < 2; mt++) {
            int row = wm * 32 + mt * 16 + li + (lq & 1) * 8;
            int col = k0 + (lq >> 1) * 8;
            uint32_t off = (uint32_t)row * ROWB + col * 2;
            ldm_x4(ah[mt], sb + OFF_AHI + off);
            ldm_x4(al[mt], sb + OFF_ALO + off);
        }
#pragma unroll
        for (int np = 0; np < 4; np++) {
            int row = wn * 64 + np * 16 + li + (lq >> 1) * 8;
            int col = k0 + (lq & 1) * 8;
            uint32_t off = (uint32_t)row * ROWB + col * 2;
            uint32_t bh[4], bl[4];
            ldm_x4(bh, sb + OFF_BHI + off);
            ldm_x4(bl, sb + OFF_BLO + off);
#pragma unroll
            for (int mt = 0; mt < 2; mt++) {
                mma_bf16(acc[mt][2 * np + 0], ah[mt], &bh[0]);
                mma_bf16(acc[mt][2 * np + 0], ah[mt], &bl[0]);
                mma_bf16(acc[mt][2 * np + 0], al[mt], &bh[0]);
                mma_bf16(acc[mt][2 * np + 1], ah[mt], &bh[2]);
                mma_bf16(acc[mt][2 * np + 1], ah[mt], &bl[2]);
                mma_bf16(acc[mt][2 * np + 1], al[mt], &bh[2]);
            }
        }
    }

    const int tg = lane >> 2;
    const int tc = (lane & 3) * 2;
#pragma unroll
    for (int mt = 0; mt < 2; mt++) {
        int r0 = block_row + wm * 32 + mt * 16 + tg;
#pragma unroll
        for (int nt = 0; nt < 8; nt++) {
            int col = wn * 64 + nt * 8 + tc;
            float bx = *(float*)(smem + OFF_BIAS + col * 4);
            float by = *(float*)(smem + OFF_BIAS + (col + 1) * 4);
            float v00 = acc[mt][nt][0] + bx, v01 = acc[mt][nt][1] + by;
            float v10 = acc[mt][nt][2] + bx, v11 = acc[mt][nt][3] + by;
            if (half_out) {
                if (r0 < M) {
                    __half2 hh = __floats2half2_rn(v00, v01);
                    Ch[(size_t)r0 * (D / 2) + (col >> 1)] = *(uint32_t*)&hh;
                }
                if (r0 + 8 < M) {
                    __half2 hh = __floats2half2_rn(v10, v11);
                    Ch[(size_t)(r0 + 8) * (D / 2) + (col >> 1)] = *(uint32_t*)&hh;
                }
            } else {
                if (r0 < M) {
                    float2 o; o.x = v00; o.y = v01;
                    *(float2*)(Cf + (size_t)r0 * D + col) = o;
                }
                if (r0 + 8 < M) {
                    float2 o; o.x = v10; o.y = v11;
                    *(float2*)(Cf + (size_t)(r0 + 8) * D + col) = o;
                }
            }
        }
    }
}

// ---------------- CSR build --------------------------------------------------
// zero + edge-dtype detect fused (block 0 / thread 0 does the 16-sample probe)
__global__ void zero_detect_kernel(const void* ei, int e, int n) {
    if (blockIdx.x == 0 && threadIdx.x == 0) {
        const long long* p = (const long long*)ei;
        int lim = (2 * e < 16) ? 2 * e : 16;
        int ok = 1;
        for (int i = 0; i < lim; ++i) {
            long long v = p[i];
            if (v < 0 || v >= NMAX) { ok = 0; break; }
        }
        g_is64 = ok;
    }
    for (int i = blockIdx.x * blockDim.x + threadIdx.x; i < n; i += gridDim.x * blockDim.x)
        g_cnt[i] = 0;
}
__global__ void hist_kernel(const void* __restrict__ ei, int e, int n) {
    int is64 = g_is64;
    for (int idx = blockIdx.x * blockDim.x + threadIdx.x; idx < e; idx += gridDim.x * blockDim.x) {
        int c = load_edge(ei, 2 * (size_t)idx + 1, is64);
        if ((unsigned)c < (unsigned)n) atomicAdd(&g_cnt[c], 1);
    }
}
__global__ void scan_kernel(int n) {
    __shared__ int warpsum[32];
    int tid  = threadIdx.x;
    int lane = tid & 31;
    int wid  = tid >> 5;
    int carry = 0;
    for (int base = 0; base < n; base += 1024) {
        int i = base + tid;
        int x = (i < n) ? g_cnt[i] : 0;
        int s = x;
#pragma unroll
        for (int off = 1; off < 32; off <<= 1) {
            int t2 = __shfl_up_sync(0xffffffffu, s, off);
            if (lane >= off) s += t2;
        }
        if (lane == 31) warpsum[wid] = s;
        __syncthreads();
        if (wid == 0) {
            int ws = warpsum[lane];
#pragma unroll
            for (int off = 1; off < 32; off <<= 1) {
                int t2 = __shfl_up_sync(0xffffffffu, ws, off);
                if (lane >= off) ws += t2;
            }
            warpsum[lane] = ws;
        }
        __syncthreads();
        int prefix = (wid > 0) ? warpsum[wid - 1] : 0;
        int excl   = s + prefix - x;
        if (i < n) {
            g_offs[i] = carry + excl;
            g_cur[i]  = carry + excl;
        }
        int total = warpsum[31];
        __syncthreads();
        carry += total;
    }
    if (tid == 0) g_offs[n] = carry;
}
__global__ void scatter_kernel(const void* __restrict__ ei, int e, int n) {
    int is64 = g_is64;
    for (int idx = blockIdx.x * blockDim.x + threadIdx.x; idx < e; idx += gridDim.x * blockDim.x) {
        int r = load_edge(ei, 2 * (size_t)idx + 0, is64);
        int c = load_edge(ei, 2 * (size_t)idx + 1, is64);
        if ((unsigned)c < (unsigned)n && (unsigned)r < (unsigned)n) {
            int pos = atomicAdd(&g_cur[c], 1);
            if ((unsigned)pos < (unsigned)EMAX) g_src[pos] = r;
        }
    }
}

// ---------------- fused per-node attention: WARP per node, fp16 k/v ----------
// Lane owns 4 contiguous dims (head = lane/4): one 8B load each for k and v.
__global__ __launch_bounds__(256)
void attn_kernel(int n) {
    int node = blockIdx.x * 8 + (threadIdx.x >> 5);
    if (node >= n) return;
    int lane = threadIdx.x & 31;
    int dim  = lane << 2;

    float4 q4 = *(const float4*)(g_q + (size_t)node * D + dim);
    q4.x *= 0.25f; q4.y *= 0.25f; q4.z *= 0.25f; q4.w *= 0.25f;

    int beg = g_offs[node];
    int end = g_offs[node + 1];

    float m = 0.f, l = 1.f;
    float4 acc = make_float4(0.f, 0.f, 0.f, 0.f);

    int r1 = (beg + 1 < end) ? g_src[beg + 1] : 0;
    uint2 ku = make_uint2(0u, 0u), vu = ku;
    if (beg < end) {
        int r0 = g_src[beg];
        ku = *(const uint2*)(g_kh + (size_t)r0 * (D / 2) + lane * 2);
        vu = *(const uint2*)(g_vh + (size_t)r0 * (D / 2) + lane * 2);
    }

    for (int j = beg; j < end; ++j) {
        int r2 = (j + 2 < end) ? g_src[j + 2] : 0;
        uint2 kn = *(const uint2*)(g_kh + (size_t)r1 * (D / 2) + lane * 2);
        uint2 vn = *(const uint2*)(g_vh + (size_t)r1 * (D / 2) + lane * 2);

        float2 k01 = __half22float2(*(const __half2*)&ku.x);
        float2 k23 = __half22float2(*(const __half2*)&ku.y);
        float2 v01 = __half22float2(*(const __half2*)&vu.x);
        float2 v23 = __half22float2(*(const __half2*)&vu.y);

        float p = q4.x * k01.x + q4.y * k01.y + q4.z * k23.x + q4.w * k23.y;
        p += __shfl_xor_sync(0xffffffffu, p, 2);
        p += __shfl_xor_sync(0xffffffffu, p, 1);

        float nm = fmaxf(m, p);
        float sc = __expf(m - nm);
        float pe = __expf(p - nm);
        l = l * sc + pe;
        acc.x = acc.x * sc + pe * v01.x;
        acc.y = acc.y * sc + pe * v01.y;
        acc.z = acc.z * sc + pe * v23.x;
        acc.w = acc.w * sc + pe * v23.y;
        m = nm;

        ku = kn; vu = vn; r1 = r2;
    }

    float inv = 1.f / (l * fmaxf((float)(end - beg), 1.f));
    float4 o;
    o.x = acc.x * inv; o.y = acc.y * inv; o.z = acc.z * inv; o.w = acc.w * inv;
    *(float4*)(g_agg + (size_t)node * D + dim) = o;
}

// ---------------- launch -----------------------------------------------------
extern "C" void kernel_launch(void* const* d_in, const int* in_sizes, int n_in,
                              void* d_out, int out_size) {
    const float* feats = (const float*)d_in[0];
    const void*  ei    = d_in[1];
    const float* Wq = (const float*)d_in[2];
    const float* bq = (const float*)d_in[3];
    const float* Wk = (const float*)d_in[4];
    const float* bk = (const float*)d_in[5];
    const float* Wv = (const float*)d_in[6];
    const float* bv = (const float*)d_in[7];
    const float* Wo = (const float*)d_in[8];
    const float* bo = (const float*)d_in[9];
    float* out = (float*)d_out;

    int n = in_sizes[0] / D;
    int e = in_sizes[1] / 2;
    if (n > NMAX || e > EMAX || n <= 0) return;

    cudaFuncSetAttribute(hmma_gemm_kernel,
                         cudaFuncAttributeMaxDynamicSharedMemorySize, GEMM_SMEM);

    // 1) zero counters + detect edge dtype (fused)
    zero_detect_kernel<<<(n + 255) / 256, 256>>>(ei, e, n);

    // 2) Q/K/V projections in ONE launch (k, v stored fp16)
    int gblocks = (n + 127) / 128;
    hmma_gemm_kernel<<<dim3(gblocks, 3), 256, GEMM_SMEM>>>(
        feats, 0, Wq, Wk, Wv, bq, bk, bv, nullptr, 0, n);

    // 3) CSR by destination
    hist_kernel<<<(e + 255) / 256, 256>>>(ei, e, n);
    scan_kernel<<<1, 1024>>>(n);
    scatter_kernel<<<(e + 255) / 256, 256>>>(ei, e, n);

    // 4) fused edge softmax + aggregation (warp per node, fp16 gathers)
    attn_kernel<<<(n + 7) / 8, 256>>>(n);

    // 5) output projection -> d_out
    hmma_gemm_kernel<<<dim3(gblocks, 1), 256, GEMM_SMEM>>>(
        nullptr, 1, Wo, Wo, Wo, bo, bo, bo, out, 3, n);
}

// round 14
// speedup vs baseline: 1.6385x; 1.1231x over previous
#include <cuda_runtime.h>
#include <cuda_bf16.h>
#include <cuda_fp16.h>
#include <cstdint>

#define D 128
#define NMAX 50048
#define EMAX 800000
#define SCAN_BLK 512

// ---------------- scratch (static device allocations; no cudaMalloc) --------
__device__ float    g_q[(size_t)NMAX * D];
__device__ uint32_t g_kh[(size_t)NMAX * (D / 2)];   // fp16x2 per entry
__device__ uint32_t g_vh[(size_t)NMAX * (D / 2)];
__device__ float    g_agg[(size_t)NMAX * D];
__device__ int      g_cnt[NMAX];
__device__ int      g_offs[NMAX + 1];
__device__ int      g_cur[NMAX];
__device__ int      g_src[EMAX];
__device__ int      g_bsum[256];
__device__ int      g_is64;

// ---------------- edge dtype handling ---------------------------------------
__device__ __forceinline__ int load_edge(const void* ei, size_t idx, int is64) {
    if (is64) return (int)((const long long*)ei)[idx];
    return ((const int*)ei)[idx];
}

// ---------------- mma.sync bf16 helpers (base ISA, sm_80+) -------------------
__device__ __forceinline__ uint32_t smem_u32(const void* p) {
    uint32_t a;
    asm("{ .reg .u64 t; cvta.to.shared.u64 t, %1; cvt.u32.u64 %0, t; }" : "=r"(a) : "l"(p));
    return a;
}
__device__ __forceinline__ void ldm_x4(uint32_t r[4], uint32_t addr) {
    asm volatile("ldmatrix.sync.aligned.m8n8.x4.shared.b16 {%0,%1,%2,%3}, [%4];"
                 : "=r"(r[0]), "=r"(r[1]), "=r"(r[2]), "=r"(r[3]) : "r"(addr));
}
__device__ __forceinline__ void mma_bf16(float d[4], const uint32_t a[4], const uint32_t b[2]) {
    asm volatile(
        "mma.sync.aligned.m16n8k16.row.col.f32.bf16.bf16.f32 "
        "{%0,%1,%2,%3}, {%4,%5,%6,%7}, {%8,%9}, {%0,%1,%2,%3};"
        : "+f"(d[0]), "+f"(d[1]), "+f"(d[2]), "+f"(d[3])
        : "r"(a[0]), "r"(a[1]), "r"(a[2]), "r"(a[3]), "r"(b[0]), "r"(b[1]));
}

// split fp32x4 -> bf16 hi (packed 2x u32) + bf16 lo
__device__ __forceinline__ void split4(float4 x, uint2& h, uint2& l) {
    __nv_bfloat16 hx = __float2bfloat16_rn(x.x);
    __nv_bfloat16 hy = __float2bfloat16_rn(x.y);
    __nv_bfloat16 hz = __float2bfloat16_rn(x.z);
    __nv_bfloat16 hw = __float2bfloat16_rn(x.w);
    __nv_bfloat16 lx = __float2bfloat16_rn(x.x - __bfloat162float(hx));
    __nv_bfloat16 ly = __float2bfloat16_rn(x.y - __bfloat162float(hy));
    __nv_bfloat16 lz = __float2bfloat16_rn(x.z - __bfloat162float(hz));
    __nv_bfloat16 lw = __float2bfloat16_rn(x.w - __bfloat162float(hw));
    h.x = (uint32_t)__bfloat16_as_ushort(hx) | ((uint32_t)__bfloat16_as_ushort(hy) << 16);
    h.y = (uint32_t)__bfloat16_as_ushort(hz) | ((uint32_t)__bfloat16_as_ushort(hw) << 16);
    l.x = (uint32_t)__bfloat16_as_ushort(lx) | ((uint32_t)__bfloat16_as_ushort(ly) << 16);
    l.y = (uint32_t)__bfloat16_as_ushort(lz) | ((uint32_t)__bfloat16_as_ushort(lw) << 16);
}

// ---------------- HMMA 3xBF16 GEMM: C[M x 128] = A @ W^T + bias -------------
// csel: 0 -> g_q (fp32), 1 -> g_kh (fp16), 2 -> g_vh (fp16), 3 -> Cext (fp32)
#define ROWB 272
#define OFF_AHI 0
#define OFF_ALO (128 * ROWB)
#define OFF_BHI (2 * 128 * ROWB)
#define OFF_BLO (3 * 128 * ROWB)
#define OFF_BIAS (4 * 128 * ROWB)
#define GEMM_SMEM (OFF_BIAS + 512)

__global__ __launch_bounds__(256, 1)
void hmma_gemm_kernel(const float* Aext, int asel,
                      const float* __restrict__ w0, const float* __restrict__ w1,
                      const float* __restrict__ w2,
                      const float* __restrict__ b0, const float* __restrict__ b1,
                      const float* __restrict__ b2,
                      float* Cext, int cbase, int M) {
    extern __shared__ char smem[];
    const uint32_t sb = smem_u32(smem);

    const int sel = blockIdx.y;
    const float* A    = asel ? g_agg : Aext;
    const float* Bw   = (sel == 0) ? w0 : (sel == 1) ? w1 : w2;
    const float* bias = (sel == 0) ? b0 : (sel == 1) ? b1 : b2;
    const int csel = cbase + sel;
    float*    Cf = (csel == 0) ? g_q : Cext;
    uint32_t* Ch = (csel == 1) ? g_kh : g_vh;
    const bool half_out = (csel == 1 || csel == 2);

    const int tid  = threadIdx.x;
    const int wid  = tid >> 5;
    const int lane = tid & 31;
    const int block_row = blockIdx.x * 128;
    const int wm = wid & 3;
    const int wn = wid >> 2;

    if (tid < 128) *(float*)(smem + OFF_BIAS + tid * 4) = bias[tid];
    for (int i = tid; i < 4096; i += 256) {
        int row = i >> 5;
        int k4  = (i & 31) << 2;
        uint32_t sboff = (uint32_t)row * ROWB + k4 * 2;
        float4 x = make_float4(0.f, 0.f, 0.f, 0.f);
        int gr = block_row + row;
        if (gr < M) x = *(const float4*)(A + (size_t)gr * D + k4);
        uint2 h, l;
        split4(x, h, l);
        *(uint2*)(smem + OFF_AHI + sboff) = h;
        *(uint2*)(smem + OFF_ALO + sboff) = l;
        float4 b = *(const float4*)(Bw + (size_t)row * D + k4);
        split4(b, h, l);
        *(uint2*)(smem + OFF_BHI + sboff) = h;
        *(uint2*)(smem + OFF_BLO + sboff) = l;
    }
    __syncthreads();

    float acc[2][8][4];
#pragma unroll
    for (int mt = 0; mt < 2; mt++)
#pragma unroll
        for (int nt = 0; nt < 8; nt++)
#pragma unroll
            for (int c = 0; c < 4; c++) acc[mt][nt][c] = 0.f;

    const int li = lane & 7;
    const int lq = lane >> 3;

    for (int ks = 0; ks < 8; ks++) {
        const int k0 = ks * 16;
        uint32_t ah[2][4], al[2][4];
#pragma unroll
        for (int mt = 0; mt < 2; mt++) {
            int row = wm * 32 + mt * 16 + li + (lq & 1) * 8;
            int col = k0 + (lq >> 1) * 8;
            uint32_t off = (uint32_t)row * ROWB + col * 2;
            ldm_x4(ah[mt], sb + OFF_AHI + off);
            ldm_x4(al[mt], sb + OFF_ALO + off);
        }
#pragma unroll
        for (int np = 0; np < 4; np++) {
            int row = wn * 64 + np * 16 + li + (lq >> 1) * 8;
            int col = k0 + (lq & 1) * 8;
            uint32_t off = (uint32_t)row * ROWB + col * 2;
            uint32_t bh[4], bl[4];
            ldm_x4(bh, sb + OFF_BHI + off);
            ldm_x4(bl, sb + OFF_BLO + off);
#pragma unroll
            for (int mt = 0; mt < 2; mt++) {
                mma_bf16(acc[mt][2 * np + 0], ah[mt], &bh[0]);
                mma_bf16(acc[mt][2 * np + 0], ah[mt], &bl[0]);
                mma_bf16(acc[mt][2 * np + 0], al[mt], &bh[0]);
                mma_bf16(acc[mt][2 * np + 1], ah[mt], &bh[2]);
                mma_bf16(acc[mt][2 * np + 1], ah[mt], &bl[2]);
                mma_bf16(acc[mt][2 * np + 1], al[mt], &bh[2]);
            }
        }
    }

    const int tg = lane >> 2;
    const int tc = (lane & 3) * 2;
#pragma unroll
    for (int mt = 0; mt < 2; mt++) {
        int r0 = block_row + wm * 32 + mt * 16 + tg;
#pragma unroll
        for (int nt = 0; nt < 8; nt++) {
            int col = wn * 64 + nt * 8 + tc;
            float bx = *(float*)(smem + OFF_BIAS + col * 4);
            float by = *(float*)(smem + OFF_BIAS + (col + 1) * 4);
            float v00 = acc[mt][nt][0] + bx, v01 = acc[mt][nt][1] + by;
            float v10 = acc[mt][nt][2] + bx, v11 = acc[mt][nt][3] + by;
            if (half_out) {
                if (r0 < M) {
                    __half2 hh = __floats2half2_rn(v00, v01);
                    Ch[(size_t)r0 * (D / 2) + (col >> 1)] = *(uint32_t*)&hh;
                }
                if (r0 + 8 < M) {
                    __half2 hh = __floats2half2_rn(v10, v11);
                    Ch[(size_t)(r0 + 8) * (D / 2) + (col >> 1)] = *(uint32_t*)&hh;
                }
            } else {
                if (r0 < M) {
                    float2 o; o.x = v00; o.y = v01;
                    *(float2*)(Cf + (size_t)r0 * D + col) = o;
                }
                if (r0 + 8 < M) {
                    float2 o; o.x = v10; o.y = v11;
                    *(float2*)(Cf + (size_t)(r0 + 8) * D + col) = o;
                }
            }
        }
    }
}

// ---------------- CSR build --------------------------------------------------
// zero + edge-dtype detect fused
__global__ void zero_detect_kernel(const void* ei, int e, int n) {
    if (blockIdx.x == 0 && threadIdx.x == 0) {
        const long long* p = (const long long*)ei;
        int lim = (2 * e < 16) ? 2 * e : 16;
        int ok = 1;
        for (int i = 0; i < lim; ++i) {
            long long v = p[i];
            if (v < 0 || v >= NMAX) { ok = 0; break; }
        }
        g_is64 = ok;
    }
    for (int i = blockIdx.x * blockDim.x + threadIdx.x; i < n; i += gridDim.x * blockDim.x)
        g_cnt[i] = 0;
}
__global__ void hist_kernel(const void* __restrict__ ei, int e, int n) {
    int is64 = g_is64;
    for (int idx = blockIdx.x * blockDim.x + threadIdx.x; idx < e; idx += gridDim.x * blockDim.x) {
        int c = load_edge(ei, 2 * (size_t)idx + 1, is64);
        if ((unsigned)c < (unsigned)n) atomicAdd(&g_cnt[c], 1);
    }
}

// ---- multi-block scan: local scans -> block-sum scan -> add offsets ----
__global__ __launch_bounds__(SCAN_BLK)
void scan_local_kernel(int n) {
    __shared__ int wsum[SCAN_BLK / 32];
    int tid  = threadIdx.x;
    int lane = tid & 31;
    int wid  = tid >> 5;
    int i = blockIdx.x * SCAN_BLK + tid;
    int x = (i < n) ? g_cnt[i] : 0;
    int s = x;
#pragma unroll
    for (int off = 1; off < 32; off <<= 1) {
        int t2 = __shfl_up_sync(0xffffffffu, s, off);
        if (lane >= off) s += t2;
    }
    if (lane == 31) wsum[wid] = s;
    __syncthreads();
    if (wid == 0) {
        int ws = (lane < SCAN_BLK / 32) ? wsum[lane] : 0;
#pragma unroll
        for (int off = 1; off < 32; off <<= 1) {
            int t2 = __shfl_up_sync(0xffffffffu, ws, off);
            if (lane >= off) ws += t2;
        }
        if (lane < SCAN_BLK / 32) wsum[lane] = ws;
    }
    __syncthreads();
    int prefix = (wid > 0) ? wsum[wid - 1] : 0;
    int excl = s + prefix - x;                 // exclusive within block
    if (i < n) g_offs[i] = excl;
    if (tid == SCAN_BLK - 1) g_bsum[blockIdx.x] = excl + x;   // block total
}

__global__ void scan_bsum_kernel(int nblocks, int n) {
    // single block, <=256 block sums
    __shared__ int sh[256];
    int tid = threadIdx.x;
    sh[tid] = (tid < nblocks) ? g_bsum[tid] : 0;
    __syncthreads();
    // Hillis-Steele inclusive scan over 256 entries
    for (int off = 1; off < 256; off <<= 1) {
        int v = (tid >= off) ? sh[tid - off] : 0;
        __syncthreads();
        sh[tid] += v;
        __syncthreads();
    }
    int incl = sh[tid];
    int x = (tid < nblocks) ? g_bsum[tid] : 0;
    if (tid < nblocks) g_bsum[tid] = incl - x;   // exclusive
    if (tid == 255) g_offs[n] = incl;            // grand total
}

__global__ __launch_bounds__(SCAN_BLK)
void scan_addoff_kernel(int n) {
    int add = g_bsum[blockIdx.x];
    int i = blockIdx.x * SCAN_BLK + threadIdx.x;
    if (i < n) {
        int v = g_offs[i] + add;
        g_offs[i] = v;
        g_cur[i]  = v;
    }
}

__global__ void scatter_kernel(const void* __restrict__ ei, int e, int n) {
    int is64 = g_is64;
    for (int idx = blockIdx.x * blockDim.x + threadIdx.x; idx < e; idx += gridDim.x * blockDim.x) {
        int r = load_edge(ei, 2 * (size_t)idx + 0, is64);
        int c = load_edge(ei, 2 * (size_t)idx + 1, is64);
        if ((unsigned)c < (unsigned)n && (unsigned)r < (unsigned)n) {
            int pos = atomicAdd(&g_cur[c], 1);
            if ((unsigned)pos < (unsigned)EMAX) g_src[pos] = r;
        }
    }
}

// ---------------- fused per-node attention: WARP per node, fp16 k/v ----------
__global__ __launch_bounds__(256)
void attn_kernel(int n) {
    int node = blockIdx.x * 8 + (threadIdx.x >> 5);
    if (node >= n) return;
    int lane = threadIdx.x & 31;
    int dim  = lane << 2;

    float4 q4 = *(const float4*)(g_q + (size_t)node * D + dim);
    q4.x *= 0.25f; q4.y *= 0.25f; q4.z *= 0.25f; q4.w *= 0.25f;

    int beg = g_offs[node];
    int end = g_offs[node + 1];

    float m = 0.f, l = 1.f;
    float4 acc = make_float4(0.f, 0.f, 0.f, 0.f);

    int r1 = (beg + 1 < end) ? g_src[beg + 1] : 0;
    uint2 ku = make_uint2(0u, 0u), vu = ku;
    if (beg < end) {
        int r0 = g_src[beg];
        ku = *(const uint2*)(g_kh + (size_t)r0 * (D / 2) + lane * 2);
        vu = *(const uint2*)(g_vh + (size_t)r0 * (D / 2) + lane * 2);
    }

    for (int j = beg; j < end; ++j) {
        int r2 = (j + 2 < end) ? g_src[j + 2] : 0;
        uint2 kn = *(const uint2*)(g_kh + (size_t)r1 * (D / 2) + lane * 2);
        uint2 vn = *(const uint2*)(g_vh + (size_t)r1 * (D / 2) + lane * 2);

        float2 k01 = __half22float2(*(const __half2*)&ku.x);
        float2 k23 = __half22float2(*(const __half2*)&ku.y);
        float2 v01 = __half22float2(*(const __half2*)&vu.x);
        float2 v23 = __half22float2(*(const __half2*)&vu.y);

        float p = q4.x * k01.x + q4.y * k01.y + q4.z * k23.x + q4.w * k23.y;
        p += __shfl_xor_sync(0xffffffffu, p, 2);
        p += __shfl_xor_sync(0xffffffffu, p, 1);

        float nm = fmaxf(m, p);
        float sc = __expf(m - nm);
        float pe = __expf(p - nm);
        l = l * sc + pe;
        acc.x = acc.x * sc + pe * v01.x;
        acc.y = acc.y * sc + pe * v01.y;
        acc.z = acc.z * sc + pe * v23.x;
        acc.w = acc.w * sc + pe * v23.y;
        m = nm;

        ku = kn; vu = vn; r1 = r2;
    }

    float inv = 1.f / (l * fmaxf((float)(end - beg), 1.f));
    float4 o;
    o.x = acc.x * inv; o.y = acc.y * inv; o.z = acc.z * inv; o.w = acc.w * inv;
    *(float4*)(g_agg + (size_t)node * D + dim) = o;
}

// ---------------- launch -----------------------------------------------------
extern "C" void kernel_launch(void* const* d_in, const int* in_sizes, int n_in,
                              void* d_out, int out_size) {
    const float* feats = (const float*)d_in[0];
    const void*  ei    = d_in[1];
    const float* Wq = (const float*)d_in[2];
    const float* bq = (const float*)d_in[3];
    const float* Wk = (const float*)d_in[4];
    const float* bk = (const float*)d_in[5];
    const float* Wv = (const float*)d_in[6];
    const float* bv = (const float*)d_in[7];
    const float* Wo = (const float*)d_in[8];
    const float* bo = (const float*)d_in[9];
    float* out = (float*)d_out;

    int n = in_sizes[0] / D;
    int e = in_sizes[1] / 2;
    if (n > NMAX || e > EMAX || n <= 0) return;

    cudaFuncSetAttribute(hmma_gemm_kernel,
                         cudaFuncAttributeMaxDynamicSharedMemorySize, GEMM_SMEM);

    // 1) zero counters + detect edge dtype (fused)
    zero_detect_kernel<<<(n + 255) / 256, 256>>>(ei, e, n);

    // 2) Q/K/V projections in ONE launch (k, v stored fp16)
    int gblocks = (n + 127) / 128;
    hmma_gemm_kernel<<<dim3(gblocks, 3), 256, GEMM_SMEM>>>(
        feats, 0, Wq, Wk, Wv, bq, bk, bv, nullptr, 0, n);

    // 3) CSR by destination (multi-block scan)
    hist_kernel<<<(e + 255) / 256, 256>>>(ei, e, n);
    int sblocks = (n + SCAN_BLK - 1) / SCAN_BLK;     // <= 98 for NMAX
    scan_local_kernel<<<sblocks, SCAN_BLK>>>(n);
    scan_bsum_kernel<<<1, 256>>>(sblocks, n);
    scan_addoff_kernel<<<sblocks, SCAN_BLK>>>(n);
    scatter_kernel<<<(e + 255) / 256, 256>>>(ei, e, n);

    // 4) fused edge softmax + aggregation (warp per node, fp16 gathers)
    attn_kernel<<<(n + 7) / 8, 256>>>(n);

    // 5) output projection -> d_out
    hmma_gemm_kernel<<<dim3(gblocks, 1), 256, GEMM_SMEM>>>(
        nullptr, 1, Wo, Wo, Wo, bo, bo, bo, out, 3, n);
}

// round 16
// speedup vs baseline: 1.6600x; 1.0131x over previous
#include <cuda_runtime.h>
#include <cuda_bf16.h>
#include <cuda_fp16.h>
#include <cstdint>

#define D 128
#define NMAX 50048
#define EMAX 800000
#define SCAN_BLK 512

// ---------------- scratch (static device allocations; no cudaMalloc) --------
__device__ float    g_q[(size_t)NMAX * D];
__device__ uint32_t g_kh[(size_t)NMAX * (D / 2)];   // fp16x2 per entry
__device__ uint32_t g_vh[(size_t)NMAX * (D / 2)];
__device__ float    g_agg[(size_t)NMAX * D];
__device__ int      g_cnt[NMAX];
__device__ int      g_offs[NMAX + 1];
__device__ int      g_cur[NMAX];
__device__ int      g_src[EMAX];
__device__ int      g_bsum[256];
__device__ int      g_is64;

// ---------------- edge dtype handling ---------------------------------------
__device__ __forceinline__ int load_edge(const void* ei, size_t idx, int is64) {
    if (is64) return (int)((const long long*)ei)[idx];
    return ((const int*)ei)[idx];
}

// ---------------- mma.sync bf16 helpers (base ISA, sm_80+) -------------------
__device__ __forceinline__ uint32_t smem_u32(const void* p) {
    uint32_t a;
    asm("{ .reg .u64 t; cvta.to.shared.u64 t, %1; cvt.u32.u64 %0, t; }" : "=r"(a) : "l"(p));
    return a;
}
__device__ __forceinline__ void ldm_x4(uint32_t r[4], uint32_t addr) {
    asm volatile("ldmatrix.sync.aligned.m8n8.x4.shared.b16 {%0,%1,%2,%3}, [%4];"
                 : "=r"(r[0]), "=r"(r[1]), "=r"(r[2]), "=r"(r[3]) : "r"(addr));
}
__device__ __forceinline__ void mma_bf16(float d[4], const uint32_t a[4], const uint32_t b[2]) {
    asm volatile(
        "mma.sync.aligned.m16n8k16.row.col.f32.bf16.bf16.f32 "
        "{%0,%1,%2,%3}, {%4,%5,%6,%7}, {%8,%9}, {%0,%1,%2,%3};"
        : "+f"(d[0]), "+f"(d[1]), "+f"(d[2]), "+f"(d[3])
        : "r"(a[0]), "r"(a[1]), "r"(a[2]), "r"(a[3]), "r"(b[0]), "r"(b[1]));
}

// split fp32x4 -> bf16 hi (packed 2x u32) + bf16 lo
__device__ __forceinline__ void split4(float4 x, uint2& h, uint2& l) {
    __nv_bfloat16 hx = __float2bfloat16_rn(x.x);
    __nv_bfloat16 hy = __float2bfloat16_rn(x.y);
    __nv_bfloat16 hz = __float2bfloat16_rn(x.z);
    __nv_bfloat16 hw = __float2bfloat16_rn(x.w);
    __nv_bfloat16 lx = __float2bfloat16_rn(x.x - __bfloat162float(hx));
    __nv_bfloat16 ly = __float2bfloat16_rn(x.y - __bfloat162float(hy));
    __nv_bfloat16 lz = __float2bfloat16_rn(x.z - __bfloat162float(hz));
    __nv_bfloat16 lw = __float2bfloat16_rn(x.w - __bfloat162float(hw));
    h.x = (uint32_t)__bfloat16_as_ushort(hx) | ((uint32_t)__bfloat16_as_ushort(hy) << 16);
    h.y = (uint32_t)__bfloat16_as_ushort(hz) | ((uint32_t)__bfloat16_as_ushort(hw) << 16);
    l.x = (uint32_t)__bfloat16_as_ushort(lx) | ((uint32_t)__bfloat16_as_ushort(ly) << 16);
    l.y = (uint32_t)__bfloat16_as_ushort(lz) | ((uint32_t)__bfloat16_as_ushort(lw) << 16);
}

// ---------------- HMMA 3xBF16 GEMM: C[M x 128] = A @ W^T + bias -------------
// csel: 0 -> g_q (fp32), 1 -> g_kh (fp16), 2 -> g_vh (fp16), 3 -> Cext (fp32)
#define ROWB 272
#define OFF_AHI 0
#define OFF_ALO (128 * ROWB)
#define OFF_BHI (2 * 128 * ROWB)
#define OFF_BLO (3 * 128 * ROWB)
#define OFF_BIAS (4 * 128 * ROWB)
#define GEMM_SMEM (OFF_BIAS + 512)

__global__ __launch_bounds__(256, 1)
void hmma_gemm_kernel(const float* Aext, int asel,
                      const float* __restrict__ w0, const float* __restrict__ w1,
                      const float* __restrict__ w2,
                      const float* __restrict__ b0, const float* __restrict__ b1,
                      const float* __restrict__ b2,
                      float* Cext, int cbase, int M) {
    extern __shared__ char smem[];
    const uint32_t sb = smem_u32(smem);

    const int sel = blockIdx.y;
    const float* A    = asel ? g_agg : Aext;
    const float* Bw   = (sel == 0) ? w0 : (sel == 1) ? w1 : w2;
    const float* bias = (sel == 0) ? b0 : (sel == 1) ? b1 : b2;
    const int csel = cbase + sel;
    float*    Cf = (csel == 0) ? g_q : Cext;
    uint32_t* Ch = (csel == 1) ? g_kh : g_vh;
    const bool half_out = (csel == 1 || csel == 2);

    const int tid  = threadIdx.x;
    const int wid  = tid >> 5;
    const int lane = tid & 31;
    const int block_row = blockIdx.x * 128;
    const int wm = wid & 3;
    const int wn = wid >> 2;

    if (tid < 128) *(float*)(smem + OFF_BIAS + tid * 4) = bias[tid];
    for (int i = tid; i < 4096; i += 256) {
        int row = i >> 5;
        int k4  = (i & 31) << 2;
        uint32_t sboff = (uint32_t)row * ROWB + k4 * 2;
        float4 x = make_float4(0.f, 0.f, 0.f, 0.f);
        int gr = block_row + row;
        if (gr < M) x = *(const float4*)(A + (size_t)gr * D + k4);
        uint2 h, l;
        split4(x, h, l);
        *(uint2*)(smem + OFF_AHI + sboff) = h;
        *(uint2*)(smem + OFF_ALO + sboff) = l;
        float4 b = *(const float4*)(Bw + (size_t)row * D + k4);
        split4(b, h, l);
        *(uint2*)(smem + OFF_BHI + sboff) = h;
        *(uint2*)(smem + OFF_BLO + sboff) = l;
    }
    __syncthreads();

    float acc[2][8][4];
#pragma unroll
    for (int mt = 0; mt < 2; mt++)
#pragma unroll
        for (int nt = 0; nt < 8; nt++)
#pragma unroll
            for (int c = 0; c < 4; c++) acc[mt][nt][c] = 0.f;

    const int li = lane & 7;
    const int lq = lane >> 3;

    for (int ks = 0; ks < 8; ks++) {
        const int k0 = ks * 16;
        uint32_t ah[2][4], al[2][4];
#pragma unroll
        for (int mt = 0; mt < 2; mt++) {
            int row = wm * 32 + mt * 16 + li + (lq & 1) * 8;
            int col = k0 + (lq >> 1) * 8;
            uint32_t off = (uint32_t)row * ROWB + col * 2;
            ldm_x4(ah[mt], sb + OFF_AHI + off);
            ldm_x4(al[mt], sb + OFF_ALO + off);
        }
#pragma unroll
        for (int np = 0; np < 4; np++) {
            int row = wn * 64 + np * 16 + li + (lq >> 1) * 8;
            int col = k0 + (lq & 1) * 8;
            uint32_t off = (uint32_t)row * ROWB + col * 2;
            uint32_t bh[4], bl[4];
            ldm_x4(bh, sb + OFF_BHI + off);
            ldm_x4(bl, sb + OFF_BLO + off);
#pragma unroll
            for (int mt = 0; mt < 2; mt++) {
                mma_bf16(acc[mt][2 * np + 0], ah[mt], &bh[0]);
                mma_bf16(acc[mt][2 * np + 0], ah[mt], &bl[0]);
                mma_bf16(acc[mt][2 * np + 0], al[mt], &bh[0]);
                mma_bf16(acc[mt][2 * np + 1], ah[mt], &bh[2]);
                mma_bf16(acc[mt][2 * np + 1], ah[mt], &bl[2]);
                mma_bf16(acc[mt][2 * np + 1], al[mt], &bh[2]);
            }
        }
    }

    const int tg = lane >> 2;
    const int tc = (lane & 3) * 2;
#pragma unroll
    for (int mt = 0; mt < 2; mt++) {
        int r0 = block_row + wm * 32 + mt * 16 + tg;
#pragma unroll
        for (int nt = 0; nt < 8; nt++) {
            int col = wn * 64 + nt * 8 + tc;
            float bx = *(float*)(smem + OFF_BIAS + col * 4);
            float by = *(float*)(smem + OFF_BIAS + (col + 1) * 4);
            float v00 = acc[mt][nt][0] + bx, v01 = acc[mt][nt][1] + by;
            float v10 = acc[mt][nt][2] + bx, v11 = acc[mt][nt][3] + by;
            if (half_out) {
                if (r0 < M) {
                    __half2 hh = __floats2half2_rn(v00, v01);
                    Ch[(size_t)r0 * (D / 2) + (col >> 1)] = *(uint32_t*)&hh;
                }
                if (r0 + 8 < M) {
                    __half2 hh = __floats2half2_rn(v10, v11);
                    Ch[(size_t)(r0 + 8) * (D / 2) + (col >> 1)] = *(uint32_t*)&hh;
                }
            } else {
                if (r0 < M) {
                    float2 o; o.x = v00; o.y = v01;
                    *(float2*)(Cf + (size_t)r0 * D + col) = o;
                }
                if (r0 + 8 < M) {
                    float2 o; o.x = v10; o.y = v11;
                    *(float2*)(Cf + (size_t)(r0 + 8) * D + col) = o;
                }
            }
        }
    }
}

// ---------------- CSR build --------------------------------------------------
__global__ void zero_detect_kernel(const void* ei, int e, int n) {
    if (blockIdx.x == 0 && threadIdx.x == 0) {
        const long long* p = (const long long*)ei;
        int lim = (2 * e < 16) ? 2 * e : 16;
        int ok = 1;
        for (int i = 0; i < lim; ++i) {
            long long v = p[i];
            if (v < 0 || v >= NMAX) { ok = 0; break; }
        }
        g_is64 = ok;
    }
    for (int i = blockIdx.x * blockDim.x + threadIdx.x; i < n; i += gridDim.x * blockDim.x)
        g_cnt[i] = 0;
}
__global__ void hist_kernel(const void* __restrict__ ei, int e, int n) {
    int is64 = g_is64;
    for (int idx = blockIdx.x * blockDim.x + threadIdx.x; idx < e; idx += gridDim.x * blockDim.x) {
        int c = load_edge(ei, 2 * (size_t)idx + 1, is64);
        if ((unsigned)c < (unsigned)n) atomicAdd(&g_cnt[c], 1);
    }
}

// ---- multi-block scan ----
__global__ __launch_bounds__(SCAN_BLK)
void scan_local_kernel(int n) {
    __shared__ int wsum[SCAN_BLK / 32];
    int tid  = threadIdx.x;
    int lane = tid & 31;
    int wid  = tid >> 5;
    int i = blockIdx.x * SCAN_BLK + tid;
    int x = (i < n) ? g_cnt[i] : 0;
    int s = x;
#pragma unroll
    for (int off = 1; off < 32; off <<= 1) {
        int t2 = __shfl_up_sync(0xffffffffu, s, off);
        if (lane >= off) s += t2;
    }
    if (lane == 31) wsum[wid] = s;
    __syncthreads();
    if (wid == 0) {
        int ws = (lane < SCAN_BLK / 32) ? wsum[lane] : 0;
#pragma unroll
        for (int off = 1; off < 32; off <<= 1) {
            int t2 = __shfl_up_sync(0xffffffffu, ws, off);
            if (lane >= off) ws += t2;
        }
        if (lane < SCAN_BLK / 32) wsum[lane] = ws;
    }
    __syncthreads();
    int prefix = (wid > 0) ? wsum[wid - 1] : 0;
    int excl = s + prefix - x;
    if (i < n) g_offs[i] = excl;
    if (tid == SCAN_BLK - 1) g_bsum[blockIdx.x] = excl + x;
}

__global__ void scan_bsum_kernel(int nblocks, int n) {
    __shared__ int sh[256];
    int tid = threadIdx.x;
    sh[tid] = (tid < nblocks) ? g_bsum[tid] : 0;
    __syncthreads();
    for (int off = 1; off < 256; off <<= 1) {
        int v = (tid >= off) ? sh[tid - off] : 0;
        __syncthreads();
        sh[tid] += v;
        __syncthreads();
    }
    int incl = sh[tid];
    int x = (tid < nblocks) ? g_bsum[tid] : 0;
    if (tid < nblocks) g_bsum[tid] = incl - x;
    if (tid == 255) g_offs[n] = incl;
}

__global__ __launch_bounds__(SCAN_BLK)
void scan_addoff_kernel(int n) {
    int add = g_bsum[blockIdx.x];
    int i = blockIdx.x * SCAN_BLK + threadIdx.x;
    if (i < n) {
        int v = g_offs[i] + add;
        g_offs[i] = v;
        g_cur[i]  = v;
    }
}

__global__ void scatter_kernel(const void* __restrict__ ei, int e, int n) {
    int is64 = g_is64;
    for (int idx = blockIdx.x * blockDim.x + threadIdx.x; idx < e; idx += gridDim.x * blockDim.x) {
        int r = load_edge(ei, 2 * (size_t)idx + 0, is64);
        int c = load_edge(ei, 2 * (size_t)idx + 1, is64);
        if ((unsigned)c < (unsigned)n && (unsigned)r < (unsigned)n) {
            int pos = atomicAdd(&g_cur[c], 1);
            if ((unsigned)pos < (unsigned)EMAX) g_src[pos] = r;
        }
    }
}

// ---------------- fused per-node attention: WARP per node, fp16 k/v ----------
// Depth-2 edge pipeline: 4 x 256B loads in flight; merged 2-edge online update.
__global__ __launch_bounds__(256)
void attn_kernel(int n) {
    int node = blockIdx.x * 8 + (threadIdx.x >> 5);
    if (node >= n) return;
    int lane = threadIdx.x & 31;
    int dim  = lane << 2;
    const size_t loff = (size_t)lane * 2;

    float4 q4 = *(const float4*)(g_q + (size_t)node * D + dim);
    q4.x *= 0.25f; q4.y *= 0.25f; q4.z *= 0.25f; q4.w *= 0.25f;

    int beg = g_offs[node];
    int end = g_offs[node + 1];
    int deg = end - beg;

    float m = 0.f, l = 1.f;
    float4 acc = make_float4(0.f, 0.f, 0.f, 0.f);

    uint2 ku0 = make_uint2(0u, 0u), vu0 = ku0, ku1 = ku0, vu1 = ku0;
    int ra = 0, rb = 0;
    if (deg > 0) {
        int r0 = g_src[beg];
        int r1 = (deg > 1) ? g_src[beg + 1] : 0;
        ku0 = *(const uint2*)(g_kh + (size_t)r0 * 64 + loff);
        vu0 = *(const uint2*)(g_vh + (size_t)r0 * 64 + loff);
        ku1 = *(const uint2*)(g_kh + (size_t)r1 * 64 + loff);
        vu1 = *(const uint2*)(g_vh + (size_t)r1 * 64 + loff);
        ra = (deg > 2) ? g_src[beg + 2] : 0;
        rb = (deg > 3) ? g_src[beg + 3] : 0;
    }

    int j = beg;
    for (; j + 1 < end; j += 2) {
        // issue next pair's loads first (4 independent 256B loads in flight)
        uint2 kn0 = *(const uint2*)(g_kh + (size_t)ra * 64 + loff);
        uint2 vn0 = *(const uint2*)(g_vh + (size_t)ra * 64 + loff);
        uint2 kn1 = *(const uint2*)(g_kh + (size_t)rb * 64 + loff);
        uint2 vn1 = *(const uint2*)(g_vh + (size_t)rb * 64 + loff);
        ra = (j + 4 < end) ? g_src[j + 4] : 0;
        rb = (j + 5 < end) ? g_src[j + 5] : 0;

        float2 a01 = __half22float2(*(const __half2*)&ku0.x);
        float2 a23 = __half22float2(*(const __half2*)&ku0.y);
        float2 b01 = __half22float2(*(const __half2*)&ku1.x);
        float2 b23 = __half22float2(*(const __half2*)&ku1.y);

        float p0 = q4.x * a01.x + q4.y * a01.y + q4.z * a23.x + q4.w * a23.y;
        float p1 = q4.x * b01.x + q4.y * b01.y + q4.z * b23.x + q4.w * b23.y;
        p0 += __shfl_xor_sync(0xffffffffu, p0, 2);
        p1 += __shfl_xor_sync(0xffffffffu, p1, 2);
        p0 += __shfl_xor_sync(0xffffffffu, p0, 1);
        p1 += __shfl_xor_sync(0xffffffffu, p1, 1);

        float2 w01 = __half22float2(*(const __half2*)&vu0.x);
        float2 w23 = __half22float2(*(const __half2*)&vu0.y);
        float2 x01 = __half22float2(*(const __half2*)&vu1.x);
        float2 x23 = __half22float2(*(const __half2*)&vu1.y);

        // merged 2-edge online softmax update
        float nm  = fmaxf(m, fmaxf(p0, p1));
        float sc  = __expf(m - nm);
        float pe0 = __expf(p0 - nm);
        float pe1 = __expf(p1 - nm);
        l = l * sc + pe0 + pe1;
        acc.x = acc.x * sc + pe0 * w01.x + pe1 * x01.x;
        acc.y = acc.y * sc + pe0 * w01.y + pe1 * x01.y;
        acc.z = acc.z * sc + pe0 * w23.x + pe1 * x23.x;
        acc.w = acc.w * sc + pe0 * w23.y + pe1 * x23.y;
        m = nm;

        ku0 = kn0; vu0 = vn0; ku1 = kn1; vu1 = vn1;
    }

    if (j < end) {   // tail edge (data already in ku0/vu0)
        float2 a01 = __half22float2(*(const __half2*)&ku0.x);
        float2 a23 = __half22float2(*(const __half2*)&ku0.y);
        float p0 = q4.x * a01.x + q4.y * a01.y + q4.z * a23.x + q4.w * a23.y;
        p0 += __shfl_xor_sync(0xffffffffu, p0, 2);
        p0 += __shfl_xor_sync(0xffffffffu, p0, 1);

        float2 w01 = __half22float2(*(const __half2*)&vu0.x);
        float2 w23 = __half22float2(*(const __half2*)&vu0.y);

        float nm  = fmaxf(m, p0);
        float sc  = __expf(m - nm);
        float pe0 = __expf(p0 - nm);
        l = l * sc + pe0;
        acc.x = acc.x * sc + pe0 * w01.x;
        acc.y = acc.y * sc + pe0 * w01.y;
        acc.z = acc.z * sc + pe0 * w23.x;
        acc.w = acc.w * sc + pe0 * w23.y;
        m = nm;
    }

    float inv = 1.f / (l * fmaxf((float)deg, 1.f));
    float4 o;
    o.x = acc.x * inv; o.y = acc.y * inv; o.z = acc.z * inv; o.w = acc.w * inv;
    *(float4*)(g_agg + (size_t)node * D + dim) = o;
}

// ---------------- launch -----------------------------------------------------
extern "C" void kernel_launch(void* const* d_in, const int* in_sizes, int n_in,
                              void* d_out, int out_size) {
    const float* feats = (const float*)d_in[0];
    const void*  ei    = d_in[1];
    const float* Wq = (const float*)d_in[2];
    const float* bq = (const float*)d_in[3];
    const float* Wk = (const float*)d_in[4];
    const float* bk = (const float*)d_in[5];
    const float* Wv = (const float*)d_in[6];
    const float* bv = (const float*)d_in[7];
    const float* Wo = (const float*)d_in[8];
    const float* bo = (const float*)d_in[9];
    float* out = (float*)d_out;

    int n = in_sizes[0] / D;
    int e = in_sizes[1] / 2;
    if (n > NMAX || e > EMAX || n <= 0) return;

    cudaFuncSetAttribute(hmma_gemm_kernel,
                         cudaFuncAttributeMaxDynamicSharedMemorySize, GEMM_SMEM);

    // 1) zero counters + detect edge dtype (fused)
    zero_detect_kernel<<<(n + 255) / 256, 256>>>(ei, e, n);

    // 2) Q/K/V projections in ONE launch (k, v stored fp16)
    int gblocks = (n + 127) / 128;
    hmma_gemm_kernel<<<dim3(gblocks, 3), 256, GEMM_SMEM>>>(
        feats, 0, Wq, Wk, Wv, bq, bk, bv, nullptr, 0, n);

    // 3) CSR by destination (multi-block scan)
    hist_kernel<<<(e + 255) / 256, 256>>>(ei, e, n);
    int sblocks = (n + SCAN_BLK - 1) / SCAN_BLK;
    scan_local_kernel<<<sblocks, SCAN_BLK>>>(n);
    scan_bsum_kernel<<<1, 256>>>(sblocks, n);
    scan_addoff_kernel<<<sblocks, SCAN_BLK>>>(n);
    scatter_kernel<<<(e + 255) / 256, 256>>>(ei, e, n);

    // 4) fused edge softmax + aggregation (warp per node, depth-2 pipeline)
    attn_kernel<<<(n + 7) / 8, 256>>>(n);

    // 5) output projection -> d_out
    hmma_gemm_kernel<<<dim3(gblocks, 1), 256, GEMM_SMEM>>>(
        nullptr, 1, Wo, Wo, Wo, bo, bo, bo, out, 3, n);
}